// round 11
// baseline (speedup 1.0000x reference)
#include <cuda_runtime.h>

#define S      256
#define NB     128
#define L      256
#define NL     64
#define VOCAB  32000

typedef unsigned long long ull;

// K1 dynamic smem:
//   TsmU2 [8][512] ulonglong2 = 65536 B  (T tail: 32 floats per thread)
//   xs    [2][2][256] float   =  4096 B  (double-buffered state vec per chain)
//   part  [2][2][256] float   =  4096 B  (partials: [chain][half][state])
//   tok   [512] int           =  2048 B
#define SMEM1  (65536 + 4096 + 4096 + 2048)

// K2 dynamic smem: esm[128][68] + osm[64][64]
#define SMEM2  (128*68*4 + 64*64*4)

// scratch
__device__ float g_fwd[L * NB * S];   // fprime[t][b][s]  (pre-e-multiply forward)
__device__ float g_bwd[L * NB * S];   // b[t][b][s]

__device__ __forceinline__ void ffma2(ull &a, ull b, ull c) {
    asm("fma.rn.f32x2 %0, %1, %2, %0;" : "+l"(a) : "l"(b), "l"(c));
}
__device__ __forceinline__ float hsum2(ull lo, ull hi) {
    float2 a = *reinterpret_cast<float2*>(&lo);
    float2 b = *reinterpret_cast<float2*>(&hi);
    return (a.x + a.y) + (b.x + b.y);
}
__device__ __forceinline__ ull packdup(float e) {
    ull r;
    asm("mov.b64 %0, {%1, %1};" : "=l"(r) : "f"(e));
    return r;
}

// no-op kernel: 3 leading nops put hmm_scan_kernel at ncu's capture index
__global__ void nop_kernel() {}

// ---------------------------------------------------------------------------
// K1 v3 (occupancy fix): 128 CTAs x 512 threads (16 warps/SM), 2 chains/CTA.
// bid<64: forward for batches (2p,2p+1); bid>=64: backward.
// Thread (h=tid>>8, s=tid&255) owns ONE state s, j in [128h, 128h+128).
// Per thread: 96 T floats in regs, 32 in smem -> ~120 regs, no spill.
// Packed fma.rn.f32x2; smem partials; 2 barriers/step; deferred output STG.
// ---------------------------------------------------------------------------
__global__ __launch_bounds__(512, 1)
void hmm_scan_kernel(const void* __restrict__ sent_raw,
                     const float* __restrict__ emb,
                     const float* __restrict__ Tm)
{
    extern __shared__ char smem_raw[];
    ulonglong2* TsmU2 = (ulonglong2*)smem_raw;              // [8][512]
    float* xs   = (float*)(smem_raw + 65536);               // [p][c][256]
    float* part = (float*)(smem_raw + 65536 + 4096);        // [c][h][256]
    int*   tok  = (int*)  (smem_raw + 65536 + 8192);        // [c][256]
    __shared__ int s_i64;

    const int  tid = threadIdx.x;
    const int  h   = tid >> 8;           // j-half
    const int  s   = tid & 255;          // owned state
    const int  j0  = h << 7;             // j-range start
    const int  bid = blockIdx.x;
    const bool bwd = (bid >= 64);
    const int  b0  = (bid & 63) * 2;

    // combine-phase role: thread handles (chain cc, state sc)
    const int  cc  = h;                  // chain index for combine
    const int  sc  = s;

    // --- detect sentences dtype (int64 vs int32) ---
    if (tid == 0) {
        const long long* s64 = (const long long*)sent_raw;
        int f = 1;
        for (int k = 0; k < 64; k++) {
            long long v = s64[k];
            if (v < 0 || v >= VOCAB) { f = 0; break; }
        }
        s_i64 = f;
    }
    __syncthreads();

    // --- tokens: tok[c*256 + t] ---
    {
        const int c   = tid >> 8;
        const int pos = tid & 255;
        if (s_i64) {
            const long long* s64 = (const long long*)sent_raw;
            tok[tid] = (int)s64[(b0 + c) * L + pos];
        } else {
            const int* s32 = (const int*)sent_raw;
            tok[tid] = s32[(b0 + c) * L + pos];
        }
    }

    // --- T slice for (state s, half h): 96 floats in regs, 32 in smem ---
    ull TrU[48];
    if (!bwd) {
        const float4* row = (const float4*)(Tm + s * S + j0);
        #pragma unroll
        for (int g = 0; g < 24; g++) ((float4*)TrU)[g] = row[g];
        const ulonglong2* rowu = (const ulonglong2*)(Tm + s * S + j0);
        #pragma unroll
        for (int g = 0; g < 8; g++) TsmU2[g * 512 + tid] = rowu[24 + g];
    } else {
        #pragma unroll
        for (int g = 0; g < 24; g++) {
            int j = j0 + 4 * g;
            ((float4*)TrU)[g] = make_float4(Tm[(j+0)*S + s], Tm[(j+1)*S + s],
                                            Tm[(j+2)*S + s], Tm[(j+3)*S + s]);
        }
        #pragma unroll
        for (int g = 0; g < 8; g++) {
            int j = j0 + 96 + 4 * g;
            float4 f4 = make_float4(Tm[(j+0)*S + s], Tm[(j+1)*S + s],
                                    Tm[(j+2)*S + s], Tm[(j+3)*S + s]);
            TsmU2[g * 512 + tid] = *reinterpret_cast<ulonglong2*>(&f4);
        }
    }

    float* outg = bwd ? g_bwd : g_fwd;

    // --- step 0: combine-role threads initialize x and outputs ---
    const int t0 = bwd ? (L - 1) : 0;
    {
        float e = emb[tok[cc * 256 + t0] * S + sc];
        outg[(t0 * NB + b0 + cc) * S + sc] = bwd ? e : 1.0f;
        xs[cc * 256 + sc] = e;   // buffer p=0
    }
    __syncthreads();

    const int dt = bwd ? -1 : 1;
    int t = t0;
    int p = 0;

    // deferred-output register
    float o = 0.f;
    int   tprev = -1;

    for (int step = 1; step < L; step++) {
        t += dt;

        // deferred output write from previous step (overlaps this matvec)
        if (tprev >= 0) {
            outg[(tprev * NB + b0 + cc) * S + sc] = o;
        }

        // e prefetch for combine role (consumed after bar1)
        float en = emb[tok[cc * 256 + t] * S + sc];

        const ulonglong2* X0 = (const ulonglong2*)(xs + p * 512 + j0);
        const ulonglong2* X1 = (const ulonglong2*)(xs + p * 512 + 256 + j0);

        ull a0l = 0, a0h = 0, a1l = 0, a1h = 0;   // chain0, chain1

        #pragma unroll
        for (int g = 0; g < 24; g++) {
            ulonglong2 x0 = X0[g];
            ulonglong2 x1 = X1[g];
            ffma2(a0l, TrU[2*g],   x0.x); ffma2(a0h, TrU[2*g+1], x0.y);
            ffma2(a1l, TrU[2*g],   x1.x); ffma2(a1h, TrU[2*g+1], x1.y);
        }
        #pragma unroll
        for (int g = 0; g < 8; g++) {
            ulonglong2 tg = TsmU2[g * 512 + tid];
            ulonglong2 x0 = X0[24 + g];
            ulonglong2 x1 = X1[24 + g];
            ffma2(a0l, tg.x, x0.x); ffma2(a0h, tg.y, x0.y);
            ffma2(a1l, tg.x, x1.x); ffma2(a1h, tg.y, x1.y);
        }

        // partials: part[c][h][s]
        part[h * 256 + s]       = hsum2(a0l, a0h);
        part[512 + h * 256 + s] = hsum2(a1l, a1h);
        __syncthreads();

        // combine: thread handles (chain cc, state sc)
        float sum = part[cc * 512 + sc] + part[cc * 512 + 256 + sc];
        float nx  = sum * en;

        // stash output for deferred write
        o = bwd ? nx : sum;
        tprev = t;

        p ^= 1;
        xs[p * 512 + cc * 256 + sc] = nx;
        __syncthreads();
    }

    // final deferred write
    outg[(tprev * NB + b0 + cc) * S + sc] = o;
}

// ---------------------------------------------------------------------------
// K2 v2 (unchanged): 256 CTAs, tile = 128 rows x 64 cols, 8x4 per thread,
// packed fma.rn.f32x2, 2 sc per iteration.
// ---------------------------------------------------------------------------
__global__ __launch_bounds__(256, 2)
void hmm_proj_kernel(const float* __restrict__ Om, float* __restrict__ outp)
{
    extern __shared__ char smem2[];
    float* esm = (float*)smem2;                  // [128][68]
    float* osm = (float*)(smem2 + 128*68*4);     // [64][64]

    const int tid = threadIdx.x;
    const int r0  = blockIdx.x * 128;
    const int rg  = tid >> 4;
    const int cg  = tid & 15;

    ull acc01[8] = {0,0,0,0,0,0,0,0};
    ull acc23[8] = {0,0,0,0,0,0,0,0};

    for (int s0 = 0; s0 < S; s0 += 64) {
        if (s0) __syncthreads();
        #pragma unroll
        for (int k = 0; k < 8; k++) {
            int id4 = k * 256 + tid;
            int rr  = id4 >> 4;
            int ss  = (id4 & 15) * 4;
            int r   = r0 + rr;
            float4 fv = *(const float4*)&g_fwd[r * S + s0 + ss];
            float4 bv = *(const float4*)&g_bwd[r * S + s0 + ss];
            float4 ev = make_float4(fv.x * bv.x, fv.y * bv.y, fv.z * bv.z, fv.w * bv.w);
            *(float4*)&esm[rr * 68 + ss] = ev;
        }
        #pragma unroll
        for (int k = 0; k < 4; k++) {
            int id4 = k * 256 + tid;
            int ss  = id4 >> 4;
            int n   = (id4 & 15) * 4;
            *(float4*)&osm[ss * 64 + n] = *(const float4*)&Om[(s0 + ss) * NL + n];
        }
        __syncthreads();

        #pragma unroll 4
        for (int sc = 0; sc < 64; sc += 2) {
            ulonglong2 ov0 = *(const ulonglong2*)&osm[sc * 64 + cg * 4];
            ulonglong2 ov1 = *(const ulonglong2*)&osm[(sc + 1) * 64 + cg * 4];
            #pragma unroll
            for (int k = 0; k < 8; k++) {
                float2 ep = *(const float2*)&esm[(rg * 8 + k) * 68 + sc];
                ull e0 = packdup(ep.x);
                ull e1 = packdup(ep.y);
                ffma2(acc01[k], e0, ov0.x);
                ffma2(acc23[k], e0, ov0.y);
                ffma2(acc01[k], e1, ov1.x);
                ffma2(acc23[k], e1, ov1.y);
            }
        }
    }

    #pragma unroll
    for (int k = 0; k < 8; k++) {
        int r  = r0 + rg * 8 + k;
        int t  = r >> 7;
        int bb = r & 127;
        float2 lo = *reinterpret_cast<float2*>(&acc01[k]);
        float2 hi = *reinterpret_cast<float2*>(&acc23[k]);
        float4 v  = make_float4(lo.x, lo.y, hi.x, hi.y);
        *(float4*)&outp[(bb * L + t) * NL + cg * 4] = v;
    }
}

extern "C" void kernel_launch(void* const* d_in, const int* in_sizes, int n_in,
                              void* d_out, int out_size)
{
    (void)in_sizes; (void)n_in; (void)out_size;
    const void*  sent = d_in[0];
    const float* emb  = (const float*)d_in[1];
    const float* Tm   = (const float*)d_in[2];
    const float* Om   = (const float*)d_in[3];
    float* outp = (float*)d_out;

    cudaFuncSetAttribute(hmm_scan_kernel,
                         cudaFuncAttributeMaxDynamicSharedMemorySize, SMEM1);
    cudaFuncSetAttribute(hmm_proj_kernel,
                         cudaFuncAttributeMaxDynamicSharedMemorySize, SMEM2);

    // 3 leading nops: hmm_scan_kernel is the ncu capture target
    nop_kernel<<<1, 32>>>();
    nop_kernel<<<1, 32>>>();
    nop_kernel<<<1, 32>>>();
    hmm_scan_kernel<<<128, 512, SMEM1>>>(sent, emb, Tm);
    hmm_proj_kernel<<<256, 256, SMEM2>>>(Om, outp);
}

// round 12
// speedup vs baseline: 1.4486x; 1.4486x over previous
#include <cuda_runtime.h>

#define S      256
#define NB     128
#define L      256
#define NL     64
#define VOCAB  32000

typedef unsigned long long ull;

// K1 dynamic smem:
//   TsmU2 [12][512] ulonglong2 = 98304 B  (T tail: 48 floats per thread)
//   xs    [2][2][256] float    =  4096 B  (double-buffered state vec per chain)
//   part  [2][4][256] float    =  8192 B  (partials: [chain][quarter][state])
//   tok   [512] int            =  2048 B
#define SMEM1  (98304 + 4096 + 8192 + 2048)

// K2 dynamic smem: esm[128][68] + osm[64][64]
#define SMEM2  (128*68*4 + 64*64*4)

// scratch
__device__ float g_fwd[L * NB * S];   // fprime[t][b][s]  (pre-e-multiply forward)
__device__ float g_bwd[L * NB * S];   // b[t][b][s]

__device__ __forceinline__ void ffma2(ull &a, ull b, ull c) {
    asm("fma.rn.f32x2 %0, %1, %2, %0;" : "+l"(a) : "l"(b), "l"(c));
}
__device__ __forceinline__ float hsum1(ull a) {
    float2 v = *reinterpret_cast<float2*>(&a);
    return v.x + v.y;
}
__device__ __forceinline__ ull packdup(float e) {
    ull r;
    asm("mov.b64 %0, {%1, %1};" : "=l"(r) : "f"(e));
    return r;
}

// no-op kernel: 3 leading nops put hmm_scan_kernel at ncu's capture index
__global__ void nop_kernel() {}

// ---------------------------------------------------------------------------
// K1 v4: 128 CTAs x 512 threads (16 warps/SM), 2 chains/CTA.
// bid<64: forward for batches (2p,2p+1); bid>=64: backward.
// Thread (q=tid>>7, u=tid&127) owns states {u, u+128} on j-quarter
// [64q, 64q+64). Per state: 40 T floats in regs, 24 in smem
// (thread total: 80 reg + 48 smem -> ~112 regs, NO spill at the 128 cap).
// Packed fma.rn.f32x2; 4-way smem partials; 2 barriers/step; deferred STG.
// ---------------------------------------------------------------------------
__global__ __launch_bounds__(512, 1)
void hmm_scan_kernel(const void* __restrict__ sent_raw,
                     const float* __restrict__ emb,
                     const float* __restrict__ Tm)
{
    extern __shared__ char smem_raw[];
    ulonglong2* TsmU2 = (ulonglong2*)smem_raw;               // [12][512]
    float* xs   = (float*)(smem_raw + 98304);                // [p][c][256]
    float* part = (float*)(smem_raw + 98304 + 4096);         // [c][q][256]
    int*   tok  = (int*)  (smem_raw + 98304 + 4096 + 8192);  // [c][256]
    __shared__ int s_i64;

    const int  tid = threadIdx.x;
    const int  q   = tid >> 7;           // j-quarter 0..3
    const int  u   = tid & 127;          // base state (also owns u+128)
    const int  j0  = q << 6;             // j-range start
    const int  bid = blockIdx.x;
    const bool bwd = (bid >= 64);
    const int  b0  = (bid & 63) * 2;

    // combine-phase role: thread handles (chain cc, state sc)
    const int  cc  = tid >> 8;
    const int  sc  = tid & 255;

    // --- detect sentences dtype (int64 vs int32) ---
    if (tid == 0) {
        const long long* s64 = (const long long*)sent_raw;
        int f = 1;
        for (int k = 0; k < 64; k++) {
            long long v = s64[k];
            if (v < 0 || v >= VOCAB) { f = 0; break; }
        }
        s_i64 = f;
    }
    __syncthreads();

    // --- tokens: tok[c*256 + t] ---
    if (s_i64) {
        const long long* s64 = (const long long*)sent_raw;
        tok[tid] = (int)s64[(b0 + cc) * L + sc];
    } else {
        const int* s32 = (const int*)sent_raw;
        tok[tid] = s32[(b0 + cc) * L + sc];
    }

    // --- T slices: states sA=u, sB=u+128, j in [j0, j0+64):
    //     per state: j [j0, j0+40) in regs, j [j0+40, j0+64) in smem ---
    ull TrU[40];   // [state k][pair]: k*20 + pp
    {
        #pragma unroll
        for (int k = 0; k < 2; k++) {
            const int sk = u + (k << 7);
            float* dst = (float*)&TrU[k * 20];
            if (!bwd) {
                const float4* row = (const float4*)(Tm + sk * S + j0);
                #pragma unroll
                for (int g = 0; g < 10; g++) ((float4*)dst)[g] = row[g];
                const ulonglong2* rowu = (const ulonglong2*)(Tm + sk * S + j0 + 40);
                #pragma unroll
                for (int g = 0; g < 6; g++)
                    TsmU2[(k * 6 + g) * 512 + tid] = rowu[g];
            } else {
                #pragma unroll
                for (int g = 0; g < 10; g++) {
                    int j = j0 + 4 * g;
                    ((float4*)dst)[g] = make_float4(
                        Tm[(j+0)*S + sk], Tm[(j+1)*S + sk],
                        Tm[(j+2)*S + sk], Tm[(j+3)*S + sk]);
                }
                #pragma unroll
                for (int g = 0; g < 6; g++) {
                    int j = j0 + 40 + 4 * g;
                    float4 f4 = make_float4(
                        Tm[(j+0)*S + sk], Tm[(j+1)*S + sk],
                        Tm[(j+2)*S + sk], Tm[(j+3)*S + sk]);
                    TsmU2[(k * 6 + g) * 512 + tid] = *reinterpret_cast<ulonglong2*>(&f4);
                }
            }
        }
    }

    float* outg = bwd ? g_bwd : g_fwd;

    // --- step 0: combine-role threads initialize x and outputs ---
    const int t0 = bwd ? (L - 1) : 0;
    {
        float e = emb[tok[cc * 256 + t0] * S + sc];
        outg[(t0 * NB + b0 + cc) * S + sc] = bwd ? e : 1.0f;
        xs[cc * 256 + sc] = e;   // buffer p=0
    }
    __syncthreads();

    const int dt = bwd ? -1 : 1;
    int t = t0;
    int p = 0;

    float o = 0.f;     // deferred output value
    int   tprev = -1;

    for (int step = 1; step < L; step++) {
        t += dt;

        // deferred output write from previous step (overlaps this matvec)
        if (tprev >= 0) {
            outg[(tprev * NB + b0 + cc) * S + sc] = o;
        }

        // e prefetch for combine role (consumed after bar1)
        float en = emb[tok[cc * 256 + t] * S + sc];

        const ulonglong2* X0 = (const ulonglong2*)(xs + p * 512) + (q * 16);
        const ulonglong2* X1 = X0 + 64;   // chain 1: +256 floats

        ull aA0 = 0, aA1 = 0, aB0 = 0, aB1 = 0;  // [state][chain]

        // register part of T: j pairs 0..19 per state
        #pragma unroll
        for (int g = 0; g < 10; g++) {
            ulonglong2 x0 = X0[g];
            ulonglong2 x1 = X1[g];
            ffma2(aA0, TrU[2*g],      x0.x); ffma2(aA0, TrU[2*g+1],      x0.y);
            ffma2(aA1, TrU[2*g],      x1.x); ffma2(aA1, TrU[2*g+1],      x1.y);
            ffma2(aB0, TrU[20+2*g],   x0.x); ffma2(aB0, TrU[20+2*g+1],   x0.y);
            ffma2(aB1, TrU[20+2*g],   x1.x); ffma2(aB1, TrU[20+2*g+1],   x1.y);
        }
        // smem part of T: j pairs 20..31 per state
        #pragma unroll
        for (int g = 0; g < 6; g++) {
            ulonglong2 tA = TsmU2[g * 512 + tid];
            ulonglong2 tB = TsmU2[(6 + g) * 512 + tid];
            ulonglong2 x0 = X0[10 + g];
            ulonglong2 x1 = X1[10 + g];
            ffma2(aA0, tA.x, x0.x); ffma2(aA0, tA.y, x0.y);
            ffma2(aA1, tA.x, x1.x); ffma2(aA1, tA.y, x1.y);
            ffma2(aB0, tB.x, x0.x); ffma2(aB0, tB.y, x0.y);
            ffma2(aB1, tB.x, x1.x); ffma2(aB1, tB.y, x1.y);
        }

        // partials: part[(c*4 + q)*256 + s]
        part[(0 * 4 + q) * 256 + u]       = hsum1(aA0);
        part[(0 * 4 + q) * 256 + u + 128] = hsum1(aB0);
        part[(1 * 4 + q) * 256 + u]       = hsum1(aA1);
        part[(1 * 4 + q) * 256 + u + 128] = hsum1(aB1);
        __syncthreads();

        // combine: thread handles (chain cc, state sc)
        const float* pc = part + cc * 1024 + sc;
        float sum = (pc[0] + pc[256]) + (pc[512] + pc[768]);
        float nx  = sum * en;

        o = bwd ? nx : sum;
        tprev = t;

        p ^= 1;
        xs[p * 512 + cc * 256 + sc] = nx;
        __syncthreads();
    }

    // final deferred write
    outg[(tprev * NB + b0 + cc) * S + sc] = o;
}

// ---------------------------------------------------------------------------
// K2 v2 (unchanged, proven 32.6us): 256 CTAs, tile = 128x64, 8x4 per thread,
// packed fma.rn.f32x2, 2 sc per iteration.
// ---------------------------------------------------------------------------
__global__ __launch_bounds__(256, 2)
void hmm_proj_kernel(const float* __restrict__ Om, float* __restrict__ outp)
{
    extern __shared__ char smem2[];
    float* esm = (float*)smem2;                  // [128][68]
    float* osm = (float*)(smem2 + 128*68*4);     // [64][64]

    const int tid = threadIdx.x;
    const int r0  = blockIdx.x * 128;
    const int rg  = tid >> 4;
    const int cg  = tid & 15;

    ull acc01[8] = {0,0,0,0,0,0,0,0};
    ull acc23[8] = {0,0,0,0,0,0,0,0};

    for (int s0 = 0; s0 < S; s0 += 64) {
        if (s0) __syncthreads();
        #pragma unroll
        for (int k = 0; k < 8; k++) {
            int id4 = k * 256 + tid;
            int rr  = id4 >> 4;
            int ss  = (id4 & 15) * 4;
            int r   = r0 + rr;
            float4 fv = *(const float4*)&g_fwd[r * S + s0 + ss];
            float4 bv = *(const float4*)&g_bwd[r * S + s0 + ss];
            float4 ev = make_float4(fv.x * bv.x, fv.y * bv.y, fv.z * bv.z, fv.w * bv.w);
            *(float4*)&esm[rr * 68 + ss] = ev;
        }
        #pragma unroll
        for (int k = 0; k < 4; k++) {
            int id4 = k * 256 + tid;
            int ss  = id4 >> 4;
            int n   = (id4 & 15) * 4;
            *(float4*)&osm[ss * 64 + n] = *(const float4*)&Om[(s0 + ss) * NL + n];
        }
        __syncthreads();

        #pragma unroll 4
        for (int sc = 0; sc < 64; sc += 2) {
            ulonglong2 ov0 = *(const ulonglong2*)&osm[sc * 64 + cg * 4];
            ulonglong2 ov1 = *(const ulonglong2*)&osm[(sc + 1) * 64 + cg * 4];
            #pragma unroll
            for (int k = 0; k < 8; k++) {
                float2 ep = *(const float2*)&esm[(rg * 8 + k) * 68 + sc];
                ull e0 = packdup(ep.x);
                ull e1 = packdup(ep.y);
                ffma2(acc01[k], e0, ov0.x);
                ffma2(acc23[k], e0, ov0.y);
                ffma2(acc01[k], e1, ov1.x);
                ffma2(acc23[k], e1, ov1.y);
            }
        }
    }

    #pragma unroll
    for (int k = 0; k < 8; k++) {
        int r  = r0 + rg * 8 + k;
        int t  = r >> 7;
        int bb = r & 127;
        float2 lo = *reinterpret_cast<float2*>(&acc01[k]);
        float2 hi = *reinterpret_cast<float2*>(&acc23[k]);
        float4 v  = make_float4(lo.x, lo.y, hi.x, hi.y);
        *(float4*)&outp[(bb * L + t) * NL + cg * 4] = v;
    }
}

extern "C" void kernel_launch(void* const* d_in, const int* in_sizes, int n_in,
                              void* d_out, int out_size)
{
    (void)in_sizes; (void)n_in; (void)out_size;
    const void*  sent = d_in[0];
    const float* emb  = (const float*)d_in[1];
    const float* Tm   = (const float*)d_in[2];
    const float* Om   = (const float*)d_in[3];
    float* outp = (float*)d_out;

    cudaFuncSetAttribute(hmm_scan_kernel,
                         cudaFuncAttributeMaxDynamicSharedMemorySize, SMEM1);
    cudaFuncSetAttribute(hmm_proj_kernel,
                         cudaFuncAttributeMaxDynamicSharedMemorySize, SMEM2);

    // 3 leading nops: hmm_scan_kernel is the ncu capture target
    nop_kernel<<<1, 32>>>();
    nop_kernel<<<1, 32>>>();
    nop_kernel<<<1, 32>>>();
    hmm_scan_kernel<<<128, 512, SMEM1>>>(sent, emb, Tm);
    hmm_proj_kernel<<<256, 256, SMEM2>>>(Om, outp);
}

// round 13
// speedup vs baseline: 1.5101x; 1.0425x over previous
#include <cuda_runtime.h>

#define S      256
#define NB     128
#define L      256
#define NL     64
#define VOCAB  32000

typedef unsigned long long ull;

// K1 dynamic smem:
//   TsmU2 [24][256] ulonglong2 = 98304 B  (T tail: 2 states x 48 j floats per thread)
//   xs    [2][2][256] float    =  4096 B
//   part  [2][2][256] float    =  4096 B
//   tok   [2][256] int         =  2048 B
#define SMEM1  (98304 + 4096 + 4096 + 2048)

// K2 dynamic smem: esm[128][68] + osm[64][64]
#define SMEM2  (128*68*4 + 64*64*4)

// scratch
__device__ float g_fwd[L * NB * S];   // fprime[t][b][s]  (pre-e-multiply forward)
__device__ float g_bwd[L * NB * S];   // b[t][b][s]

__device__ __forceinline__ void ffma2(ull &a, ull b, ull c) {
    asm("fma.rn.f32x2 %0, %1, %2, %0;" : "+l"(a) : "l"(b), "l"(c));
}
__device__ __forceinline__ float hsum2(ull lo, ull hi) {
    float2 a = *reinterpret_cast<float2*>(&lo);
    float2 b = *reinterpret_cast<float2*>(&hi);
    return (a.x + a.y) + (b.x + b.y);
}
__device__ __forceinline__ ull packdup(float e) {
    ull r;
    asm("mov.b64 %0, {%1, %1};" : "=l"(r) : "f"(e));
    return r;
}

// no-op kernel: 3 leading nops keep hmm_scan_kernel at ncu's capture index
__global__ void nop_kernel() {}

// ---------------------------------------------------------------------------
// K1 (R6 structure; T split retuned 80reg/48smem per state to kill spills):
// 128 CTAs x 256 threads, 2 chains/CTA. bid<64: fwd batches (2p,2p+1);
// bid>=64: bwd. Thread (h=tid>>7, u=tid&127) owns states {u, u+128},
// j in [128h, 128h+128). Packed fma.rn.f32x2; smem partials; 2 barriers/step;
// deferred output STG.
// ---------------------------------------------------------------------------
__global__ __launch_bounds__(256, 1)
void hmm_scan_kernel(const void* __restrict__ sent_raw,
                     const float* __restrict__ emb,
                     const float* __restrict__ Tm)
{
    extern __shared__ char smem_raw[];
    ulonglong2* TsmU2 = (ulonglong2*)smem_raw;               // [24][256]
    float* xs   = (float*)(smem_raw + 98304);                // [p][c][256]
    float* part = (float*)(smem_raw + 98304 + 4096);         // [c][h][256]
    int*   tok  = (int*)  (smem_raw + 98304 + 8192);         // [c][256]
    __shared__ int s_i64;

    const int  tid = threadIdx.x;
    const int  h   = tid >> 7;
    const int  u   = tid & 127;
    const int  j0  = h << 7;
    const int  bid = blockIdx.x;
    const bool bwd = (bid >= 64);
    const int  b0  = (bid & 63) * 2;
    const int  b1  = b0 + 1;

    // --- detect sentences dtype (int64 vs int32) ---
    if (tid == 0) {
        const long long* s64 = (const long long*)sent_raw;
        int f = 1;
        for (int k = 0; k < 64; k++) {
            long long v = s64[k];
            if (v < 0 || v >= VOCAB) { f = 0; break; }
        }
        s_i64 = f;
    }
    __syncthreads();

    // --- tokens for both chains ---
    if (s_i64) {
        const long long* s64 = (const long long*)sent_raw;
        tok[tid]       = (int)s64[b0 * L + tid];
        tok[256 + tid] = (int)s64[b1 * L + tid];
    } else {
        const int* s32 = (const int*)sent_raw;
        tok[tid]       = s32[b0 * L + tid];
        tok[256 + tid] = s32[b1 * L + tid];
    }

    // --- T slices: states u (A) / u+128 (B), j in [j0, j0+128):
    //     80 floats in regs (40 ull) + 48 floats in smem (12 u2) per state ---
    ull TrA[40], TrB[40];
    if (!bwd) {
        const float4* rowA = (const float4*)(Tm + u * S + j0);
        const float4* rowB = (const float4*)(Tm + (u + 128) * S + j0);
        #pragma unroll
        for (int g = 0; g < 20; g++) {
            ((float4*)TrA)[g] = rowA[g];
            ((float4*)TrB)[g] = rowB[g];
        }
        #pragma unroll
        for (int g = 0; g < 12; g++) {
            TsmU2[g * 256 + tid]        = ((const ulonglong2*)rowA)[20 + g];
            TsmU2[(12 + g) * 256 + tid] = ((const ulonglong2*)rowB)[20 + g];
        }
    } else {
        #pragma unroll
        for (int g = 0; g < 20; g++) {
            int j = j0 + 4 * g;
            ((float4*)TrA)[g] = make_float4(Tm[(j+0)*S + u],       Tm[(j+1)*S + u],
                                            Tm[(j+2)*S + u],       Tm[(j+3)*S + u]);
            ((float4*)TrB)[g] = make_float4(Tm[(j+0)*S + u + 128], Tm[(j+1)*S + u + 128],
                                            Tm[(j+2)*S + u + 128], Tm[(j+3)*S + u + 128]);
        }
        #pragma unroll
        for (int g = 0; g < 12; g++) {
            int j = j0 + 80 + 4 * g;
            float4 a4 = make_float4(Tm[(j+0)*S + u],       Tm[(j+1)*S + u],
                                    Tm[(j+2)*S + u],       Tm[(j+3)*S + u]);
            float4 b4 = make_float4(Tm[(j+0)*S + u + 128], Tm[(j+1)*S + u + 128],
                                    Tm[(j+2)*S + u + 128], Tm[(j+3)*S + u + 128]);
            TsmU2[g * 256 + tid]        = *reinterpret_cast<ulonglong2*>(&a4);
            TsmU2[(12 + g) * 256 + tid] = *reinterpret_cast<ulonglong2*>(&b4);
        }
    }

    float* outg = bwd ? g_bwd : g_fwd;

    // --- step 0 ---
    const int t0 = bwd ? (L - 1) : 0;
    {
        float e0 = emb[tok[t0] * S + tid];
        float e1 = emb[tok[256 + t0] * S + tid];
        if (!bwd) {
            outg[(t0 * NB + b0) * S + tid] = 1.0f;    // fprime[0] = 1
            outg[(t0 * NB + b1) * S + tid] = 1.0f;
        } else {
            outg[(t0 * NB + b0) * S + tid] = e0;      // b[L-1] = e[L-1]
            outg[(t0 * NB + b1) * S + tid] = e1;
        }
        xs[tid]       = e0;
        xs[256 + tid] = e1;
    }
    __syncthreads();

    const int dt = bwd ? -1 : 1;
    int t = t0;
    int p = 0;

    float o0 = 0.f, o1 = 0.f;
    int   tprev = -1;

    for (int step = 1; step < L; step++) {
        t += dt;

        // deferred output write from previous step (overlaps this matvec)
        if (tprev >= 0) {
            outg[(tprev * NB + b0) * S + tid] = o0;
            outg[(tprev * NB + b1) * S + tid] = o1;
        }

        // e prefetch: consumed only after bar1
        float en0 = emb[tok[t] * S + tid];
        float en1 = emb[tok[256 + t] * S + tid];

        const ulonglong2* X0 = (const ulonglong2*)(xs + p * 512 + j0);
        const ulonglong2* X1 = (const ulonglong2*)(xs + p * 512 + 256 + j0);

        ull a00l = 0, a00h = 0, a01l = 0, a01h = 0;   // state u:     chain0, chain1
        ull a10l = 0, a10h = 0, a11l = 0, a11h = 0;   // state u+128

        // register part of T: j pairs 0..39 per state
        #pragma unroll
        for (int g = 0; g < 20; g++) {
            ulonglong2 x0 = X0[g];
            ulonglong2 x1 = X1[g];
            ffma2(a00l, TrA[2*g],   x0.x); ffma2(a00h, TrA[2*g+1], x0.y);
            ffma2(a01l, TrA[2*g],   x1.x); ffma2(a01h, TrA[2*g+1], x1.y);
            ffma2(a10l, TrB[2*g],   x0.x); ffma2(a10h, TrB[2*g+1], x0.y);
            ffma2(a11l, TrB[2*g],   x1.x); ffma2(a11h, TrB[2*g+1], x1.y);
        }
        // smem part of T: j pairs 40..63 per state
        #pragma unroll
        for (int g = 0; g < 12; g++) {
            ulonglong2 tA = TsmU2[g * 256 + tid];
            ulonglong2 tB = TsmU2[(12 + g) * 256 + tid];
            ulonglong2 x0 = X0[20 + g];
            ulonglong2 x1 = X1[20 + g];
            ffma2(a00l, tA.x, x0.x); ffma2(a00h, tA.y, x0.y);
            ffma2(a01l, tA.x, x1.x); ffma2(a01h, tA.y, x1.y);
            ffma2(a10l, tB.x, x0.x); ffma2(a10h, tB.y, x0.y);
            ffma2(a11l, tB.x, x1.x); ffma2(a11h, tB.y, x1.y);
        }

        // partials: part[c][h][s]
        part[h * 256 + u]             = hsum2(a00l, a00h);
        part[h * 256 + u + 128]       = hsum2(a10l, a10h);
        part[512 + h * 256 + u]       = hsum2(a01l, a01h);
        part[512 + h * 256 + u + 128] = hsum2(a11l, a11h);
        __syncthreads();

        // combine: thread tid handles state tid, both chains
        float s0 = part[tid]       + part[256 + tid];
        float s1 = part[512 + tid] + part[768 + tid];
        float nx0 = s0 * en0;
        float nx1 = s1 * en1;

        o0 = bwd ? nx0 : s0;
        o1 = bwd ? nx1 : s1;
        tprev = t;

        p ^= 1;
        xs[p * 512 + tid]       = nx0;
        xs[p * 512 + 256 + tid] = nx1;
        __syncthreads();
    }

    // final deferred write
    outg[(tprev * NB + b0) * S + tid] = o0;
    outg[(tprev * NB + b1) * S + tid] = o1;
}

// ---------------------------------------------------------------------------
// K2 v3: 256 CTAs, tile = 128 rows x 64 cols, 8x4 per thread, packed
// fma.rn.f32x2; inner loop now 4 sc per iteration with float4 e-loads
// (inner LDS wavefronts per output -33%).
// ---------------------------------------------------------------------------
__global__ __launch_bounds__(256, 2)
void hmm_proj_kernel(const float* __restrict__ Om, float* __restrict__ outp)
{
    extern __shared__ char smem2[];
    float* esm = (float*)smem2;                  // [128][68]
    float* osm = (float*)(smem2 + 128*68*4);     // [64][64]

    const int tid = threadIdx.x;
    const int r0  = blockIdx.x * 128;
    const int rg  = tid >> 4;
    const int cg  = tid & 15;

    ull acc01[8] = {0,0,0,0,0,0,0,0};
    ull acc23[8] = {0,0,0,0,0,0,0,0};

    for (int s0 = 0; s0 < S; s0 += 64) {
        if (s0) __syncthreads();
        #pragma unroll
        for (int k = 0; k < 8; k++) {
            int id4 = k * 256 + tid;
            int rr  = id4 >> 4;
            int ss  = (id4 & 15) * 4;
            int r   = r0 + rr;
            float4 fv = *(const float4*)&g_fwd[r * S + s0 + ss];
            float4 bv = *(const float4*)&g_bwd[r * S + s0 + ss];
            float4 ev = make_float4(fv.x * bv.x, fv.y * bv.y, fv.z * bv.z, fv.w * bv.w);
            *(float4*)&esm[rr * 68 + ss] = ev;
        }
        #pragma unroll
        for (int k = 0; k < 4; k++) {
            int id4 = k * 256 + tid;
            int ss  = id4 >> 4;
            int n   = (id4 & 15) * 4;
            *(float4*)&osm[ss * 64 + n] = *(const float4*)&Om[(s0 + ss) * NL + n];
        }
        __syncthreads();

        #pragma unroll 2
        for (int sc = 0; sc < 64; sc += 4) {
            ulonglong2 ov0 = *(const ulonglong2*)&osm[(sc + 0) * 64 + cg * 4];
            ulonglong2 ov1 = *(const ulonglong2*)&osm[(sc + 1) * 64 + cg * 4];
            ulonglong2 ov2 = *(const ulonglong2*)&osm[(sc + 2) * 64 + cg * 4];
            ulonglong2 ov3 = *(const ulonglong2*)&osm[(sc + 3) * 64 + cg * 4];
            #pragma unroll
            for (int k = 0; k < 8; k++) {
                float4 ep = *(const float4*)&esm[(rg * 8 + k) * 68 + sc];
                ull e0 = packdup(ep.x);
                ull e1 = packdup(ep.y);
                ull e2 = packdup(ep.z);
                ull e3 = packdup(ep.w);
                ffma2(acc01[k], e0, ov0.x);
                ffma2(acc23[k], e0, ov0.y);
                ffma2(acc01[k], e1, ov1.x);
                ffma2(acc23[k], e1, ov1.y);
                ffma2(acc01[k], e2, ov2.x);
                ffma2(acc23[k], e2, ov2.y);
                ffma2(acc01[k], e3, ov3.x);
                ffma2(acc23[k], e3, ov3.y);
            }
        }
    }

    #pragma unroll
    for (int k = 0; k < 8; k++) {
        int r  = r0 + rg * 8 + k;
        int t  = r >> 7;
        int bb = r & 127;
        float2 lo = *reinterpret_cast<float2*>(&acc01[k]);
        float2 hi = *reinterpret_cast<float2*>(&acc23[k]);
        float4 v  = make_float4(lo.x, lo.y, hi.x, hi.y);
        *(float4*)&outp[(bb * L + t) * NL + cg * 4] = v;
    }
}

extern "C" void kernel_launch(void* const* d_in, const int* in_sizes, int n_in,
                              void* d_out, int out_size)
{
    (void)in_sizes; (void)n_in; (void)out_size;
    const void*  sent = d_in[0];
    const float* emb  = (const float*)d_in[1];
    const float* Tm   = (const float*)d_in[2];
    const float* Om   = (const float*)d_in[3];
    float* outp = (float*)d_out;

    cudaFuncSetAttribute(hmm_scan_kernel,
                         cudaFuncAttributeMaxDynamicSharedMemorySize, SMEM1);
    cudaFuncSetAttribute(hmm_proj_kernel,
                         cudaFuncAttributeMaxDynamicSharedMemorySize, SMEM2);

    // 3 leading nops: hmm_scan_kernel is the ncu capture target
    nop_kernel<<<1, 32>>>();
    nop_kernel<<<1, 32>>>();
    nop_kernel<<<1, 32>>>();
    hmm_scan_kernel<<<128, 256, SMEM1>>>(sent, emb, Tm);
    hmm_proj_kernel<<<256, 256, SMEM2>>>(Om, outp);
}

// round 14
// speedup vs baseline: 1.5263x; 1.0107x over previous
#include <cuda_runtime.h>

#define S      256
#define NB     128
#define L      256
#define NL     64
#define VOCAB  32000

typedef unsigned long long ull;

// K1 dynamic smem:
//   TsmU2 [24][256] ulonglong2 = 98304 B  (T tail: 2 states x 48 j floats per thread)
//   xs    [2][2][256] float    =  4096 B
//   part  [2][2][256] float    =  4096 B
//   tok   [2][256] int         =  2048 B
#define SMEM1  (98304 + 4096 + 4096 + 2048)

// K2 dynamic smem: esm[128][68] + osm[64][64]
#define SMEM2  (128*68*4 + 64*64*4)

// scratch
__device__ float g_fwd[L * NB * S];   // fprime[t][b][s]  (pre-e-multiply forward)
__device__ float g_bwd[L * NB * S];   // b[t][b][s]

__device__ __forceinline__ void ffma2(ull &a, ull b, ull c) {
    asm("fma.rn.f32x2 %0, %1, %2, %0;" : "+l"(a) : "l"(b), "l"(c));
}
__device__ __forceinline__ float hsum2(ull lo, ull hi) {
    float2 a = *reinterpret_cast<float2*>(&lo);
    float2 b = *reinterpret_cast<float2*>(&hi);
    return (a.x + a.y) + (b.x + b.y);
}
__device__ __forceinline__ ull packdup(float e) {
    ull r;
    asm("mov.b64 %0, {%1, %1};" : "=l"(r) : "f"(e));
    return r;
}

// ---------------------------------------------------------------------------
// K1 (best known: R12 structure, 294.6us, regs=252 no-spill):
// 128 CTAs x 256 threads, 2 chains/CTA. bid<64: fwd batches (2p,2p+1);
// bid>=64: bwd. Thread (h=tid>>7, u=tid&127) owns states {u, u+128},
// j in [128h, 128h+128), T split 80 reg / 48 smem floats per state.
// Packed fma.rn.f32x2; smem partials; 2 barriers/step; deferred output STG.
// ---------------------------------------------------------------------------
__global__ __launch_bounds__(256, 1)
void hmm_scan_kernel(const void* __restrict__ sent_raw,
                     const float* __restrict__ emb,
                     const float* __restrict__ Tm)
{
    extern __shared__ char smem_raw[];
    ulonglong2* TsmU2 = (ulonglong2*)smem_raw;               // [24][256]
    float* xs   = (float*)(smem_raw + 98304);                // [p][c][256]
    float* part = (float*)(smem_raw + 98304 + 4096);         // [c][h][256]
    int*   tok  = (int*)  (smem_raw + 98304 + 8192);         // [c][256]
    __shared__ int s_i64;

    const int  tid = threadIdx.x;
    const int  h   = tid >> 7;
    const int  u   = tid & 127;
    const int  j0  = h << 7;
    const int  bid = blockIdx.x;
    const bool bwd = (bid >= 64);
    const int  b0  = (bid & 63) * 2;
    const int  b1  = b0 + 1;

    // --- detect sentences dtype (int64 vs int32) ---
    if (tid == 0) {
        const long long* s64 = (const long long*)sent_raw;
        int f = 1;
        for (int k = 0; k < 64; k++) {
            long long v = s64[k];
            if (v < 0 || v >= VOCAB) { f = 0; break; }
        }
        s_i64 = f;
    }
    __syncthreads();

    // --- tokens for both chains ---
    if (s_i64) {
        const long long* s64 = (const long long*)sent_raw;
        tok[tid]       = (int)s64[b0 * L + tid];
        tok[256 + tid] = (int)s64[b1 * L + tid];
    } else {
        const int* s32 = (const int*)sent_raw;
        tok[tid]       = s32[b0 * L + tid];
        tok[256 + tid] = s32[b1 * L + tid];
    }

    // --- T slices: states u (A) / u+128 (B), j in [j0, j0+128):
    //     80 floats in regs (40 ull) + 48 floats in smem (12 u2) per state ---
    ull TrA[40], TrB[40];
    if (!bwd) {
        const float4* rowA = (const float4*)(Tm + u * S + j0);
        const float4* rowB = (const float4*)(Tm + (u + 128) * S + j0);
        #pragma unroll
        for (int g = 0; g < 20; g++) {
            ((float4*)TrA)[g] = rowA[g];
            ((float4*)TrB)[g] = rowB[g];
        }
        #pragma unroll
        for (int g = 0; g < 12; g++) {
            TsmU2[g * 256 + tid]        = ((const ulonglong2*)rowA)[20 + g];
            TsmU2[(12 + g) * 256 + tid] = ((const ulonglong2*)rowB)[20 + g];
        }
    } else {
        #pragma unroll
        for (int g = 0; g < 20; g++) {
            int j = j0 + 4 * g;
            ((float4*)TrA)[g] = make_float4(Tm[(j+0)*S + u],       Tm[(j+1)*S + u],
                                            Tm[(j+2)*S + u],       Tm[(j+3)*S + u]);
            ((float4*)TrB)[g] = make_float4(Tm[(j+0)*S + u + 128], Tm[(j+1)*S + u + 128],
                                            Tm[(j+2)*S + u + 128], Tm[(j+3)*S + u + 128]);
        }
        #pragma unroll
        for (int g = 0; g < 12; g++) {
            int j = j0 + 80 + 4 * g;
            float4 a4 = make_float4(Tm[(j+0)*S + u],       Tm[(j+1)*S + u],
                                    Tm[(j+2)*S + u],       Tm[(j+3)*S + u]);
            float4 b4 = make_float4(Tm[(j+0)*S + u + 128], Tm[(j+1)*S + u + 128],
                                    Tm[(j+2)*S + u + 128], Tm[(j+3)*S + u + 128]);
            TsmU2[g * 256 + tid]        = *reinterpret_cast<ulonglong2*>(&a4);
            TsmU2[(12 + g) * 256 + tid] = *reinterpret_cast<ulonglong2*>(&b4);
        }
    }

    float* outg = bwd ? g_bwd : g_fwd;

    // --- step 0 ---
    const int t0 = bwd ? (L - 1) : 0;
    {
        float e0 = emb[tok[t0] * S + tid];
        float e1 = emb[tok[256 + t0] * S + tid];
        if (!bwd) {
            outg[(t0 * NB + b0) * S + tid] = 1.0f;    // fprime[0] = 1
            outg[(t0 * NB + b1) * S + tid] = 1.0f;
        } else {
            outg[(t0 * NB + b0) * S + tid] = e0;      // b[L-1] = e[L-1]
            outg[(t0 * NB + b1) * S + tid] = e1;
        }
        xs[tid]       = e0;
        xs[256 + tid] = e1;
    }
    __syncthreads();

    const int dt = bwd ? -1 : 1;
    int t = t0;
    int p = 0;

    float o0 = 0.f, o1 = 0.f;
    int   tprev = -1;

    for (int step = 1; step < L; step++) {
        t += dt;

        // deferred output write from previous step (overlaps this matvec)
        if (tprev >= 0) {
            outg[(tprev * NB + b0) * S + tid] = o0;
            outg[(tprev * NB + b1) * S + tid] = o1;
        }

        // e prefetch: consumed only after bar1
        float en0 = emb[tok[t] * S + tid];
        float en1 = emb[tok[256 + t] * S + tid];

        const ulonglong2* X0 = (const ulonglong2*)(xs + p * 512 + j0);
        const ulonglong2* X1 = (const ulonglong2*)(xs + p * 512 + 256 + j0);

        ull a00l = 0, a00h = 0, a01l = 0, a01h = 0;   // state u:     chain0, chain1
        ull a10l = 0, a10h = 0, a11l = 0, a11h = 0;   // state u+128

        // register part of T: j pairs 0..39 per state
        #pragma unroll
        for (int g = 0; g < 20; g++) {
            ulonglong2 x0 = X0[g];
            ulonglong2 x1 = X1[g];
            ffma2(a00l, TrA[2*g],   x0.x); ffma2(a00h, TrA[2*g+1], x0.y);
            ffma2(a01l, TrA[2*g],   x1.x); ffma2(a01h, TrA[2*g+1], x1.y);
            ffma2(a10l, TrB[2*g],   x0.x); ffma2(a10h, TrB[2*g+1], x0.y);
            ffma2(a11l, TrB[2*g],   x1.x); ffma2(a11h, TrB[2*g+1], x1.y);
        }
        // smem part of T: j pairs 40..63 per state
        #pragma unroll
        for (int g = 0; g < 12; g++) {
            ulonglong2 tA = TsmU2[g * 256 + tid];
            ulonglong2 tB = TsmU2[(12 + g) * 256 + tid];
            ulonglong2 x0 = X0[20 + g];
            ulonglong2 x1 = X1[20 + g];
            ffma2(a00l, tA.x, x0.x); ffma2(a00h, tA.y, x0.y);
            ffma2(a01l, tA.x, x1.x); ffma2(a01h, tA.y, x1.y);
            ffma2(a10l, tB.x, x0.x); ffma2(a10h, tB.y, x0.y);
            ffma2(a11l, tB.x, x1.x); ffma2(a11h, tB.y, x1.y);
        }

        // partials: part[c][h][s]
        part[h * 256 + u]             = hsum2(a00l, a00h);
        part[h * 256 + u + 128]       = hsum2(a10l, a10h);
        part[512 + h * 256 + u]       = hsum2(a01l, a01h);
        part[512 + h * 256 + u + 128] = hsum2(a11l, a11h);
        __syncthreads();

        // combine: thread tid handles state tid, both chains
        float s0 = part[tid]       + part[256 + tid];
        float s1 = part[512 + tid] + part[768 + tid];
        float nx0 = s0 * en0;
        float nx1 = s1 * en1;

        o0 = bwd ? nx0 : s0;
        o1 = bwd ? nx1 : s1;
        tprev = t;

        p ^= 1;
        xs[p * 512 + tid]       = nx0;
        xs[p * 512 + 256 + tid] = nx1;
        __syncthreads();
    }

    // final deferred write
    outg[(tprev * NB + b0) * S + tid] = o0;
    outg[(tprev * NB + b1) * S + tid] = o1;
}

// ---------------------------------------------------------------------------
// K2 v2 (best measured): 256 CTAs, tile = 128 rows x 64 cols, 8x4 per
// thread, packed fma.rn.f32x2, 2 sc per iteration with float2 e-loads.
// ---------------------------------------------------------------------------
__global__ __launch_bounds__(256, 2)
void hmm_proj_kernel(const float* __restrict__ Om, float* __restrict__ outp)
{
    extern __shared__ char smem2[];
    float* esm = (float*)smem2;                  // [128][68]
    float* osm = (float*)(smem2 + 128*68*4);     // [64][64]

    const int tid = threadIdx.x;
    const int r0  = blockIdx.x * 128;
    const int rg  = tid >> 4;
    const int cg  = tid & 15;

    ull acc01[8] = {0,0,0,0,0,0,0,0};
    ull acc23[8] = {0,0,0,0,0,0,0,0};

    for (int s0 = 0; s0 < S; s0 += 64) {
        if (s0) __syncthreads();
        #pragma unroll
        for (int k = 0; k < 8; k++) {
            int id4 = k * 256 + tid;
            int rr  = id4 >> 4;
            int ss  = (id4 & 15) * 4;
            int r   = r0 + rr;
            float4 fv = *(const float4*)&g_fwd[r * S + s0 + ss];
            float4 bv = *(const float4*)&g_bwd[r * S + s0 + ss];
            float4 ev = make_float4(fv.x * bv.x, fv.y * bv.y, fv.z * bv.z, fv.w * bv.w);
            *(float4*)&esm[rr * 68 + ss] = ev;
        }
        #pragma unroll
        for (int k = 0; k < 4; k++) {
            int id4 = k * 256 + tid;
            int ss  = id4 >> 4;
            int n   = (id4 & 15) * 4;
            *(float4*)&osm[ss * 64 + n] = *(const float4*)&Om[(s0 + ss) * NL + n];
        }
        __syncthreads();

        #pragma unroll 4
        for (int sc = 0; sc < 64; sc += 2) {
            ulonglong2 ov0 = *(const ulonglong2*)&osm[sc * 64 + cg * 4];
            ulonglong2 ov1 = *(const ulonglong2*)&osm[(sc + 1) * 64 + cg * 4];
            #pragma unroll
            for (int k = 0; k < 8; k++) {
                float2 ep = *(const float2*)&esm[(rg * 8 + k) * 68 + sc];
                ull e0 = packdup(ep.x);
                ull e1 = packdup(ep.y);
                ffma2(acc01[k], e0, ov0.x);
                ffma2(acc23[k], e0, ov0.y);
                ffma2(acc01[k], e1, ov1.x);
                ffma2(acc23[k], e1, ov1.y);
            }
        }
    }

    #pragma unroll
    for (int k = 0; k < 8; k++) {
        int r  = r0 + rg * 8 + k;
        int t  = r >> 7;
        int bb = r & 127;
        float2 lo = *reinterpret_cast<float2*>(&acc01[k]);
        float2 hi = *reinterpret_cast<float2*>(&acc23[k]);
        float4 v  = make_float4(lo.x, lo.y, hi.x, hi.y);
        *(float4*)&outp[(bb * L + t) * NL + cg * 4] = v;
    }
}

extern "C" void kernel_launch(void* const* d_in, const int* in_sizes, int n_in,
                              void* d_out, int out_size)
{
    (void)in_sizes; (void)n_in; (void)out_size;
    const void*  sent = d_in[0];
    const float* emb  = (const float*)d_in[1];
    const float* Tm   = (const float*)d_in[2];
    const float* Om   = (const float*)d_in[3];
    float* outp = (float*)d_out;

    cudaFuncSetAttribute(hmm_scan_kernel,
                         cudaFuncAttributeMaxDynamicSharedMemorySize, SMEM1);
    cudaFuncSetAttribute(hmm_proj_kernel,
                         cudaFuncAttributeMaxDynamicSharedMemorySize, SMEM2);

    hmm_scan_kernel<<<128, 256, SMEM1>>>(sent, emb, Tm);
    hmm_proj_kernel<<<256, 256, SMEM2>>>(Om, outp);
}